// round 13
// baseline (speedup 1.0000x reference)
#include <cuda_runtime.h>
#include <cuda_bf16.h>

// Gumbel-Sinkhorn, u/v diagonal-scaling, ONE MATRIX PER WARP, smem-assisted.
// X0 = exp((sigmoid(gamma)+noise - rowmax)/T); 20x {u=1/(X0 v); v=1/(X0^T u)};
// out = u_i X0_ij v_j.
// Lane l=(q=l>>3, s=l&7) holds T[k][j] = packed (X0[s+8k][16q+2j], [..+2j+1]).
// u/v are kept in per-warp smem in NATURAL order; operand gathers are LDS
// (broadcast), only the partial-sum reductions use shfl halving butterflies.
// Butterfly output ownership: row-reduce -> lane owns rows (s+16*perm[q], +8),
// perm = 2-bit swap of q {0,2,1,3}; col-reduce -> lane owns cols
// (16q+2*jstar, +1), jstar = bitrev3(s). Owners write results to smem.
// No __syncthreads anywhere; per-warp smem + __syncwarp only.

#define EX2F(d, x)       asm("ex2.approx.f32 %0, %1;" : "=f"(d) : "f"(x))
#define RCPF(d, x)       asm("rcp.approx.f32 %0, %1;" : "=f"(d) : "f"(x))
#define PACK2(d, lo, hi) asm("mov.b64 %0, {%1, %2};" : "=l"(d) : "f"(lo), "f"(hi))
#define UNPACK2(lo, hi, s) asm("mov.b64 {%0, %1}, %2;" : "=f"(lo), "=f"(hi) : "l"(s))
#define FMA2(acc, a, b)  asm("fma.rn.f32x2 %0, %1, %2, %0;" : "+l"(acc) : "l"(a), "l"(b))
#define ADD2(d, a, b)    asm("add.rn.f32x2 %0, %1, %2;" : "=l"(d) : "l"(a), "l"(b))
#define MUL2(d, a, b)    asm("mul.rn.f32x2 %0, %1, %2;" : "=l"(d) : "l"(a), "l"(b))

__device__ float g_sig[4096];  // sigmoid(gamma)

__global__ void sigmoid_kernel(const float* __restrict__ gamma) {
    int i = blockIdx.x * blockDim.x + threadIdx.x;
    if (i < 4096) {
        float x = gamma[i];
        float e; EX2F(e, -x * 1.4426950408889634f);
        float s; RCPF(s, 1.0f + e);
        g_sig[i] = s;
    }
}

__device__ __forceinline__ unsigned long long sxor(unsigned long long v, int m) {
    return __shfl_xor_sync(0xffffffffu, v, m);
}

// Reduce 8 per-row scalars over the 4 q-lanes (xor 8, xor 16) with halving.
// Lane ends owning the pair for rows (s + 16*perm[q], +8), perm={0,2,1,3}.
__device__ __forceinline__ unsigned long long row_reduce(const float (&pr)[8],
                                                         int qb0, int qb1) {
    unsigned long long P0, P1, P2, P3;
    PACK2(P0, pr[0], pr[1]); PACK2(P1, pr[2], pr[3]);
    PACK2(P2, pr[4], pr[5]); PACK2(P3, pr[6], pr[7]);
    unsigned long long s0 = qb0 ? P0 : P2;
    unsigned long long k0 = qb0 ? P2 : P0;
    unsigned long long s1 = qb0 ? P1 : P3;
    unsigned long long k1 = qb0 ? P3 : P1;
    unsigned long long r0 = sxor(s0, 8);
    unsigned long long r1 = sxor(s1, 8);
    unsigned long long Q0, Q1;
    ADD2(Q0, k0, r0);
    ADD2(Q1, k1, r1);
    unsigned long long s2 = qb1 ? Q0 : Q1;
    unsigned long long k2 = qb1 ? Q1 : Q0;
    unsigned long long r2 = sxor(s2, 16);
    unsigned long long y; ADD2(y, k2, r2);
    return y;
}

__global__ void __launch_bounds__(128) sinkhorn_kernel(const float* __restrict__ noise,
                                                       float* __restrict__ out,
                                                       int num_matrices) {
    __shared__ __align__(16) float sU[4][64];
    __shared__ __align__(16) float sV[4][64];

    const int w = threadIdx.x >> 5;
    const int lane = threadIdx.x & 31;
    const int b = blockIdx.x * 4 + w;
    if (b >= num_matrices) return;            // whole-warp exit
    const int q = lane >> 3;                  // 0..3 col-quarter
    const int s = lane & 7;                   // 0..7
    const int qb0 = q & 1, qb1 = q & 2;
    const int sb0 = s & 1, sb1 = s & 2, sb2 = s & 4;
    const int r0own = s + 16 * (((q & 1) << 1) | (q >> 1));          // row-owner base
    const int cown = 16 * q + 2 * (((s & 1) << 2) | (s & 2) | (s >> 2));  // col-owner base

    const float* __restrict__ A = noise + (size_t)b * 4096 + (s * 64 + q * 16);
    const float* __restrict__ G = g_sig + (s * 64 + q * 16);
    float* __restrict__ O = out + (size_t)b * 4096 + (s * 64 + q * 16);

    const float C = 14.426950408889634f;      // log2(e)/0.1

    unsigned long long T[8][8];               // the tile, packed col-pairs
    float pr[8];

    // ---- build tile: load, add gamma, per-row max (cross-lane), exp, row sums ----
#pragma unroll
    for (int k = 0; k < 8; k++) {
        float4 av[4];
#pragma unroll
        for (int j2 = 0; j2 < 4; j2++) {
            float4 n = *reinterpret_cast<const float4*>(A + k * 512 + j2 * 4);
            float4 g = *reinterpret_cast<const float4*>(G + k * 512 + j2 * 4);
            av[j2] = make_float4(n.x + g.x, n.y + g.y, n.z + g.z, n.w + g.w);
        }
        float m01 = fmaxf(fmaxf(av[0].x, av[0].y), fmaxf(av[0].z, av[0].w));
        float m23 = fmaxf(fmaxf(av[1].x, av[1].y), fmaxf(av[1].z, av[1].w));
        float m45 = fmaxf(fmaxf(av[2].x, av[2].y), fmaxf(av[2].z, av[2].w));
        float m67 = fmaxf(fmaxf(av[3].x, av[3].y), fmaxf(av[3].z, av[3].w));
        float m = fmaxf(fmaxf(m01, m23), fmaxf(m45, m67));
        m = fmaxf(m, __shfl_xor_sync(0xffffffffu, m, 8));
        m = fmaxf(m, __shfl_xor_sync(0xffffffffu, m, 16));
        float mc = m * C;
        unsigned long long rs = 0ull;
#pragma unroll
        for (int j2 = 0; j2 < 4; j2++) {
            float e0, e1, e2, e3;
            EX2F(e0, fmaf(av[j2].x, C, -mc));
            EX2F(e1, fmaf(av[j2].y, C, -mc));
            EX2F(e2, fmaf(av[j2].z, C, -mc));
            EX2F(e3, fmaf(av[j2].w, C, -mc));
            unsigned long long t0, t1;
            PACK2(t0, e0, e1); PACK2(t1, e2, e3);
            T[k][2 * j2] = t0; T[k][2 * j2 + 1] = t1;
            ADD2(rs, rs, t0); ADD2(rs, rs, t1);
        }
        float lo, hi; UNPACK2(lo, hi, rs);
        pr[k] = lo + hi;
    }

    // u0 = 1/(X0 * ones); owner writes its 2 rows to sU (natural order)
    {
        unsigned long long y = row_reduce(pr, qb0, qb1);
        float lo, hi; UNPACK2(lo, hi, y);
        float a, c; RCPF(a, lo); RCPF(c, hi);
        sU[w][r0own] = a;
        sU[w][r0own + 8] = c;
    }
    __syncwarp();

    // ---- 20 iterations: u0 done; loop does v then (except last) u ----
#pragma unroll 1
    for (int it = 0; it < 20; ++it) {
        // ---- col update: v = 1/(X0^T u); lane k-partial covers rows s+8k ----
        unsigned long long acc[8];
#pragma unroll
        for (int j = 0; j < 8; j++) acc[j] = 0ull;
#pragma unroll
        for (int k = 0; k < 8; k++) {
            float uu = sU[w][s + 8 * k];
            unsigned long long ub; PACK2(ub, uu, uu);
#pragma unroll
            for (int j = 0; j < 8; j++) FMA2(acc[j], T[k][j], ub);
        }
        // halving butterfly over s-lanes: xor 1, 2, 4
        unsigned long long B[4];
#pragma unroll
        for (int m = 0; m < 4; m++) {
            unsigned long long snd = sb0 ? acc[m] : acc[m + 4];
            unsigned long long kp  = sb0 ? acc[m + 4] : acc[m];
            unsigned long long r = sxor(snd, 1);
            ADD2(B[m], kp, r);
        }
        unsigned long long Cc[2];
#pragma unroll
        for (int m = 0; m < 2; m++) {
            unsigned long long snd = sb1 ? B[m] : B[m + 2];
            unsigned long long kp  = sb1 ? B[m + 2] : B[m];
            unsigned long long r = sxor(snd, 2);
            ADD2(Cc[m], kp, r);
        }
        {
            unsigned long long snd = sb2 ? Cc[0] : Cc[1];
            unsigned long long kp  = sb2 ? Cc[1] : Cc[0];
            unsigned long long r = sxor(snd, 4);
            unsigned long long z; ADD2(z, kp, r);
            float lo, hi; UNPACK2(lo, hi, z);
            float a, c; RCPF(a, lo); RCPF(c, hi);
            unsigned long long vp; PACK2(vp, a, c);
            *reinterpret_cast<unsigned long long*>(&sV[w][cown]) = vp;
        }
        __syncwarp();
        if (it == 19) break;                  // 20th col-normalize is the last op

        // ---- row update: u = 1/(X0 v) ----
        unsigned long long accR[8];
#pragma unroll
        for (int k = 0; k < 8; k++) accR[k] = 0ull;
#pragma unroll
        for (int j2 = 0; j2 < 4; j2++) {
            float4 vv = *reinterpret_cast<const float4*>(&sV[w][16 * q + 4 * j2]);
            unsigned long long v0, v1;
            PACK2(v0, vv.x, vv.y);
            PACK2(v1, vv.z, vv.w);
#pragma unroll
            for (int k = 0; k < 8; k++) {
                FMA2(accR[k], T[k][2 * j2], v0);
                FMA2(accR[k], T[k][2 * j2 + 1], v1);
            }
        }
        float pr2[8];
#pragma unroll
        for (int k = 0; k < 8; k++) {
            float lo, hi; UNPACK2(lo, hi, accR[k]);
            pr2[k] = lo + hi;
        }
        unsigned long long y = row_reduce(pr2, qb0, qb1);
        {
            float lo, hi; UNPACK2(lo, hi, y);
            float a, c; RCPF(a, lo); RCPF(c, hi);
            sU[w][r0own] = a;
            sU[w][r0own + 8] = c;
        }
        __syncwarp();
    }

    // ---- epilogue: out[r][c] = u_r * X0[r][c] * v_c ----
    unsigned long long vq[8];
#pragma unroll
    for (int j2 = 0; j2 < 4; j2++) {
        float4 vv = *reinterpret_cast<const float4*>(&sV[w][16 * q + 4 * j2]);
        PACK2(vq[2 * j2], vv.x, vv.y);
        PACK2(vq[2 * j2 + 1], vv.z, vv.w);
    }
#pragma unroll
    for (int k = 0; k < 8; k++) {
        float uu = sU[w][s + 8 * k];
        unsigned long long ub; PACK2(ub, uu, uu);
#pragma unroll
        for (int j2 = 0; j2 < 4; j2++) {
            unsigned long long p0, p1;
            MUL2(p0, T[k][2 * j2], ub);     MUL2(p0, p0, vq[2 * j2]);
            MUL2(p1, T[k][2 * j2 + 1], ub); MUL2(p1, p1, vq[2 * j2 + 1]);
            float4 o;
            UNPACK2(o.x, o.y, p0);
            UNPACK2(o.z, o.w, p1);
            *reinterpret_cast<float4*>(O + k * 512 + j2 * 4) = o;
        }
    }
}

extern "C" void kernel_launch(void* const* d_in, const int* in_sizes, int n_in,
                              void* d_out, int out_size) {
    const float* gamma = (const float*)d_in[0];
    const float* noise = (const float*)d_in[1];
    int s0 = in_sizes[0], s1 = (n_in >= 2) ? in_sizes[1] : 0;
    if (s0 > s1) {  // defensive: gamma is the small one (4096 elements)
        const float* tmp = gamma; gamma = noise; noise = tmp;
        int ts = s0; s0 = s1; s1 = ts;
    }
    int num_matrices = s1 / 4096;  // 8192 for the reference shapes
    float* out = (float*)d_out;

    sigmoid_kernel<<<16, 256>>>(gamma);
    sinkhorn_kernel<<<(num_matrices + 3) / 4, 128>>>(noise, out, num_matrices);
}